// round 5
// baseline (speedup 1.0000x reference)
#include <cuda_runtime.h>
#include <math.h>

// StatefulSynapseNet, R5: R4 structure (weights in __constant__, lane=t GEMMs,
// f32x2 FFMA) + occupancy raised to 10 blocks/SM and both shared transposes
// vectorized to 64-bit ops (pitch 34 -> conflict-free LDS.64/STS.64 rows).

typedef unsigned long long ull;

__device__ __forceinline__ ull pack2(float lo, float hi) {
    ull r; asm("mov.b64 %0, {%1,%2};" : "=l"(r) : "f"(lo), "f"(hi)); return r;
}
__device__ __forceinline__ void unpack2(ull v, float& lo, float& hi) {
    asm("mov.b64 {%0,%1}, %2;" : "=f"(lo), "=f"(hi) : "l"(v));
}
__device__ __forceinline__ ull ffma2(ull a, ull b, ull c) {
    ull d; asm("fma.rn.f32x2 %0, %1, %2, %3;" : "=l"(d) : "l"(a), "l"(b), "l"(c)); return d;
}

#define T_DIM 28
#define F_DIM 28
#define C1 32
#define C2 10
#define WARPS 4
#define HP 34              // even pitch: rows 8B-aligned; 8B-bank stride 17 -> conflict-free
#define H2P 29             // odd pitch: conflict-free scalar rows + columns
#define REGION (T_DIM*HP + C2*H2P + 2)   // 952 + 290 + 2 = 1244 floats per warp

// constant-block layout (floats)
#define OFF_W1T 0          // W1 transposed: [f*32 + o] = W1[o*28+f]
#define OFF_W2  896        // [j*32 + o]
#define OFF_B1  1216       // 32
#define OFF_B2  1248       // 10
#define OFF_ITAU 1258      // sigmoid(w_syn)
#define CP_SIZE 1280

__constant__ __align__(16) float c_P[CP_SIZE];
__device__   __align__(16) float g_stage[CP_SIZE];

__global__ void setup_kernel(const float* __restrict__ W1,
                             const float* __restrict__ b1,
                             const float* __restrict__ w_syn,
                             const float* __restrict__ W2,
                             const float* __restrict__ b2)
{
    int i = threadIdx.x;
    for (int idx = i; idx < C1 * F_DIM; idx += 1024) {
        int f = idx >> 5, o = idx & 31;
        g_stage[OFF_W1T + idx] = W1[o * F_DIM + f];
    }
    for (int idx = i; idx < C2 * C1; idx += 1024)
        g_stage[OFF_W2 + idx] = W2[idx];
    if (i < C1) g_stage[OFF_B1 + i] = b1[i];
    if (i < C2) g_stage[OFF_B2 + i] = b2[i];
    if (i == 0) g_stage[OFF_ITAU] = 1.0f / (1.0f + expf(-w_syn[0]));
}

__global__ __launch_bounds__(WARPS * 32, 10)
void snn_kernel(const float* __restrict__ x, float* __restrict__ out, int N)
{
    __shared__ float sh[WARPS * REGION];
    const int lane = threadIdx.x & 31;
    const int warp = threadIdx.x >> 5;
    const int n = blockIdx.x * WARPS + warp;
    if (n >= N) return;

    float* shw = sh + warp * REGION;          // H/y buffer [t][o], pitch 34
    float* sh2 = shw + T_DIM * HP;            // h2 buffer  [j][t], pitch 29
    const bool tl = (lane < T_DIM);

    // ---- phase 1: lane = t. acc[p] = (H[t][2p], H[t][2p+1]) ----
    ull acc[C1 / 2];
#pragma unroll
    for (int p = 0; p < C1 / 2; ++p)
        acc[p] = *reinterpret_cast<const ull*>(c_P + OFF_B1 + 2 * p);

    const float* xcol = x + (size_t)n * (F_DIM * T_DIM) + lane;
#pragma unroll 7
    for (int f = 0; f < F_DIM; ++f) {
        float xv = tl ? __ldg(xcol + f * T_DIM) : 0.0f;   // coalesced, lane-distinct
        ull xp = pack2(xv, xv);
        const ulonglong2* wq = reinterpret_cast<const ulonglong2*>(c_P + OFF_W1T + f * C1);
#pragma unroll
        for (int q = 0; q < 8; ++q) {                     // uniform const loads
            ulonglong2 w = wq[q];
            acc[2 * q]     = ffma2(xp, w.x, acc[2 * q]);
            acc[2 * q + 1] = ffma2(xp, w.y, acc[2 * q + 1]);
        }
    }
    // transpose H to shared: 16 packed STS.64, conflict-free (8B-bank stride 17)
    if (tl) {
        ull* hr = reinterpret_cast<ull*>(shw + lane * HP);
#pragma unroll
        for (int p = 0; p < C1 / 2; ++p) hr[p] = acc[p];
    }
    __syncwarp();

    // ---- IF scan + synapse filter: lane = o, y written in place over H ----
    {
        const float itau = c_P[OFF_ITAU];
        float v = 0.0f, g = 0.0f;
#pragma unroll
        for (int t = 0; t < T_DIM; ++t) {
            float h = shw[t * HP + lane];       // column read, conflict-free
            v += h;
            bool sp = (v >= 1.0f);
            v = sp ? 0.0f : v;                  // hard reset
            g = fmaf(g, -itau, g) + (sp ? 1.0f : 0.0f);
            shw[t * HP + lane] = g;             // y[t][o]
        }
    }
    __syncwarp();

    // ---- phase 2: lane = t, W2 from constant, y via 16 LDS.64 ----
    if (tl) {
        ull yq[C1 / 2];
        const ull* yr = reinterpret_cast<const ull*>(shw + lane * HP);
#pragma unroll
        for (int q = 0; q < C1 / 2; ++q) yq[q] = yr[q];
#pragma unroll
        for (int j = 0; j < C2; ++j) {
            ull a2 = 0ULL;                      // (0.f, 0.f)
            const ulonglong2* wq2 = reinterpret_cast<const ulonglong2*>(c_P + OFF_W2 + j * C1);
#pragma unroll
            for (int q = 0; q < 8; ++q) {
                ulonglong2 w = wq2[q];
                a2 = ffma2(yq[2 * q],     w.x, a2);
                a2 = ffma2(yq[2 * q + 1], w.y, a2);
            }
            float a, b; unpack2(a2, a, b);
            sh2[j * H2P + lane] = a + b + c_P[OFF_B2 + j];
        }
    }
    __syncwarp();

    // ---- second IF scan + mean: lane = j ----
    if (lane < C2) {
        float v = 0.0f, cnt = 0.0f;
#pragma unroll
        for (int t = 0; t < T_DIM; ++t) {
            v += sh2[lane * H2P + t];
            if (v >= 1.0f) { cnt += 1.0f; v = 0.0f; }
        }
        out[(size_t)n * C2 + lane] = cnt * (1.0f / 28.0f);
    }
}

extern "C" void kernel_launch(void* const* d_in, const int* in_sizes, int n_in,
                              void* d_out, int out_size)
{
    const float* x     = (const float*)d_in[0];
    const float* W1    = (const float*)d_in[1];
    const float* b1    = (const float*)d_in[2];
    const float* w_syn = (const float*)d_in[3];
    const float* W2    = (const float*)d_in[4];
    const float* b2    = (const float*)d_in[5];
    float* out = (float*)d_out;

    const int N = in_sizes[0] / (F_DIM * T_DIM);

    setup_kernel<<<1, 1024>>>(W1, b1, w_syn, W2, b2);

    void* sp = nullptr;
    cudaGetSymbolAddress(&sp, g_stage);
    cudaMemcpyToSymbolAsync(c_P, sp, CP_SIZE * sizeof(float), 0,
                            cudaMemcpyDeviceToDevice, 0);

    const int blocks = (N + WARPS - 1) / WARPS;
    snn_kernel<<<blocks, WARPS * 32>>>(x, out, N);
}

// round 6
// speedup vs baseline: 1.3813x; 1.3813x over previous
#include <cuda_runtime.h>
#include <math.h>

// StatefulSynapseNet, R6: exact R4 structure (weights in __constant__, lane=t
// GEMMs via fma.rn.f32x2, scalar pitch-33 transposes) but each warp processes
// TWO samples so every constant-port weight load (LDC, rt=8 GPR-dest) is
// amortized over both samples' FFMA2s.

typedef unsigned long long ull;

__device__ __forceinline__ ull pack2(float lo, float hi) {
    ull r; asm("mov.b64 %0, {%1,%2};" : "=l"(r) : "f"(lo), "f"(hi)); return r;
}
__device__ __forceinline__ void unpack2(ull v, float& lo, float& hi) {
    asm("mov.b64 {%0,%1}, %2;" : "=f"(lo), "=f"(hi) : "l"(v));
}
__device__ __forceinline__ ull ffma2(ull a, ull b, ull c) {
    ull d; asm("fma.rn.f32x2 %0, %1, %2, %3;" : "=l"(d) : "l"(a), "l"(b), "l"(c)); return d;
}

#define T_DIM 28
#define F_DIM 28
#define C1 32
#define C2 10
#define WARPS 4
#define SPW 2              // samples per warp
#define HP 33              // H/y pitch (R4-proven conflict-free scalar pattern)
#define H2P 29
#define REGION (T_DIM*HP + C2*H2P + 2)   // 924 + 290 + 2 = 1216 floats

// constant-block layout (floats)
#define OFF_W1T 0          // W1 transposed: [f*32 + o] = W1[o*28+f]
#define OFF_W2  896        // [j*32 + o]
#define OFF_B1  1216
#define OFF_B2  1248
#define OFF_ITAU 1258
#define CP_SIZE 1280

__constant__ __align__(16) float c_P[CP_SIZE];
__device__   __align__(16) float g_stage[CP_SIZE];

__global__ void setup_kernel(const float* __restrict__ W1,
                             const float* __restrict__ b1,
                             const float* __restrict__ w_syn,
                             const float* __restrict__ W2,
                             const float* __restrict__ b2)
{
    int i = threadIdx.x;
    for (int idx = i; idx < C1 * F_DIM; idx += 1024) {
        int f = idx >> 5, o = idx & 31;
        g_stage[OFF_W1T + idx] = W1[o * F_DIM + f];
    }
    for (int idx = i; idx < C2 * C1; idx += 1024)
        g_stage[OFF_W2 + idx] = W2[idx];
    if (i < C1) g_stage[OFF_B1 + i] = b1[i];
    if (i < C2) g_stage[OFF_B2 + i] = b2[i];
    if (i == 0) g_stage[OFF_ITAU] = 1.0f / (1.0f + expf(-w_syn[0]));
}

__global__ __launch_bounds__(WARPS * 32, 5)
void snn_kernel(const float* __restrict__ x, float* __restrict__ out, int N)
{
    __shared__ float sh[WARPS * SPW * REGION];
    const int lane = threadIdx.x & 31;
    const int warp = threadIdx.x >> 5;
    const int n0 = (blockIdx.x * WARPS + warp) * SPW;
    if (n0 >= N) return;
    const bool has_b = (n0 + 1 < N);
    const int n1 = has_b ? (n0 + 1) : n0;

    float* shA = sh + warp * (SPW * REGION);  // sample a: H/y [t][o] p33, h2 [j][t] p29
    float* shB = shA + REGION;                // sample b
    float* sh2A = shA + T_DIM * HP;
    float* sh2B = shB + T_DIM * HP;
    const bool tl = (lane < T_DIM);

    // ---- phase 1: lane = t; dual-sample accumulators ----
    ull accA[C1 / 2], accB[C1 / 2];
#pragma unroll
    for (int p = 0; p < C1 / 2; ++p) {
        ull b = *reinterpret_cast<const ull*>(c_P + OFF_B1 + 2 * p);
        accA[p] = b; accB[p] = b;
    }

    const float* xa = x + (size_t)n0 * (F_DIM * T_DIM) + lane;
    const float* xb = x + (size_t)n1 * (F_DIM * T_DIM) + lane;
#pragma unroll 4
    for (int f = 0; f < F_DIM; ++f) {
        float xva = tl ? __ldg(xa + f * T_DIM) : 0.0f;
        float xvb = tl ? __ldg(xb + f * T_DIM) : 0.0f;
        ull xpa = pack2(xva, xva);
        ull xpb = pack2(xvb, xvb);
        const ulonglong2* wq = reinterpret_cast<const ulonglong2*>(c_P + OFF_W1T + f * C1);
#pragma unroll
        for (int q = 0; q < 8; ++q) {          // each weight load feeds 4 FFMA2
            ulonglong2 w = wq[q];
            accA[2 * q]     = ffma2(xpa, w.x, accA[2 * q]);
            accB[2 * q]     = ffma2(xpb, w.x, accB[2 * q]);
            accA[2 * q + 1] = ffma2(xpa, w.y, accA[2 * q + 1]);
            accB[2 * q + 1] = ffma2(xpb, w.y, accB[2 * q + 1]);
        }
    }
    // transpose H to shared (scalar, R4 pattern)
    if (tl) {
#pragma unroll
        for (int p = 0; p < C1 / 2; ++p) {
            float a0, a1, b0, b1v;
            unpack2(accA[p], a0, a1);
            unpack2(accB[p], b0, b1v);
            shA[lane * HP + 2 * p]     = a0;
            shA[lane * HP + 2 * p + 1] = a1;
            shB[lane * HP + 2 * p]     = b0;
            shB[lane * HP + 2 * p + 1] = b1v;
        }
    }
    __syncwarp();

    // ---- IF scan + synapse filter: lane = o, both samples interleaved ----
    {
        const float itau = c_P[OFF_ITAU];
        float va = 0.0f, ga = 0.0f, vb = 0.0f, gb = 0.0f;
#pragma unroll
        for (int t = 0; t < T_DIM; ++t) {
            float ha = shA[t * HP + lane];
            float hb = shB[t * HP + lane];
            va += ha;                          vb += hb;
            bool sa = (va >= 1.0f);            bool sb = (vb >= 1.0f);
            va = sa ? 0.0f : va;               vb = sb ? 0.0f : vb;
            ga = fmaf(ga, -itau, ga) + (sa ? 1.0f : 0.0f);
            gb = fmaf(gb, -itau, gb) + (sb ? 1.0f : 0.0f);
            shA[t * HP + lane] = ga;
            shB[t * HP + lane] = gb;
        }
    }
    __syncwarp();

    // ---- phase 2: lane = t; W2 loads shared across both samples ----
    if (tl) {
        ull yqa[C1 / 2], yqb[C1 / 2];
        const float* ya = shA + lane * HP;
        const float* yb = shB + lane * HP;
#pragma unroll
        for (int q = 0; q < C1 / 2; ++q) {
            yqa[q] = pack2(ya[2 * q], ya[2 * q + 1]);
            yqb[q] = pack2(yb[2 * q], yb[2 * q + 1]);
        }
#pragma unroll
        for (int j = 0; j < C2; ++j) {
            ull a2 = 0ULL, b2a = 0ULL;
            const ulonglong2* wq2 = reinterpret_cast<const ulonglong2*>(c_P + OFF_W2 + j * C1);
#pragma unroll
            for (int q = 0; q < 8; ++q) {
                ulonglong2 w = wq2[q];
                a2  = ffma2(yqa[2 * q],     w.x, a2);
                b2a = ffma2(yqb[2 * q],     w.x, b2a);
                a2  = ffma2(yqa[2 * q + 1], w.y, a2);
                b2a = ffma2(yqb[2 * q + 1], w.y, b2a);
            }
            float u0, u1, v0, v1;
            unpack2(a2, u0, u1);
            unpack2(b2a, v0, v1);
            float bj = c_P[OFF_B2 + j];
            sh2A[j * H2P + lane] = u0 + u1 + bj;
            sh2B[j * H2P + lane] = v0 + v1 + bj;
        }
    }
    __syncwarp();

    // ---- second IF scan + mean: 20 lanes (j = lane&15, sample = lane>>4) ----
    {
        int sj = lane & 15;
        int ss = lane >> 4;
        if (sj < C2 && (ss == 0 || has_b)) {
            const float* h2 = ss ? sh2B : sh2A;
            float v = 0.0f, cnt = 0.0f;
#pragma unroll
            for (int t = 0; t < T_DIM; ++t) {
                v += h2[sj * H2P + t];
                if (v >= 1.0f) { cnt += 1.0f; v = 0.0f; }
            }
            int nn = ss ? n1 : n0;
            out[(size_t)nn * C2 + sj] = cnt * (1.0f / 28.0f);
        }
    }
}

extern "C" void kernel_launch(void* const* d_in, const int* in_sizes, int n_in,
                              void* d_out, int out_size)
{
    const float* x     = (const float*)d_in[0];
    const float* W1    = (const float*)d_in[1];
    const float* b1    = (const float*)d_in[2];
    const float* w_syn = (const float*)d_in[3];
    const float* W2    = (const float*)d_in[4];
    const float* b2    = (const float*)d_in[5];
    float* out = (float*)d_out;

    const int N = in_sizes[0] / (F_DIM * T_DIM);

    setup_kernel<<<1, 1024>>>(W1, b1, w_syn, W2, b2);

    void* sp = nullptr;
    cudaGetSymbolAddress(&sp, g_stage);
    cudaMemcpyToSymbolAsync(c_P, sp, CP_SIZE * sizeof(float), 0,
                            cudaMemcpyDeviceToDevice, 0);

    const int spb = WARPS * SPW;
    const int blocks = (N + spb - 1) / spb;
    snn_kernel<<<blocks, WARPS * 32>>>(x, out, N);
}